// round 16
// baseline (speedup 1.0000x reference)
#include <cuda_runtime.h>
#include <cuda_bf16.h>
#include <cstdint>

#define BCH   10
#define HH    320
#define WW    1024
#define PTS   500
#define DENSE 2000
#define KMEAN 10
#define NPTS  (BCH * PTS)
#define CHUNKS 500            // int4 chunks per point
#define CH_PER_W 250          // chunks per warp

// Window: by in [-7,7] (15 rows), bx in [-11,11] (23 cols), padded to 32 cols.
#define WROWS 15
#define WCOLS 23
#define WSLOTS (WROWS * 32)   // 480
#define FULLM 0xFFFFFFFFu

// TWO WARPS PER POINT (CTA=64), ZERO ATOMICS.
// Window -> smem once; each warp LDS-gathers its 1000 samples into sv[32]
// registers; k-means runs on registers with a 1-barrier/iter cross-warp merge.
__global__ __launch_bounds__(64)
void rsbsp_kernel(const float* __restrict__ disp,
                  const float* __restrict__ fore,
                  const int*   __restrict__ cxs,
                  const int*   __restrict__ cys,
                  const int*   __restrict__ bxs,
                  const int*   __restrict__ bys,
                  float*       __restrict__ out)
{
    __shared__ float win[WSLOTS];
    __shared__ float s_m[2][3];          // per-warp {mx, mn, stot}
    __shared__ float s_it[2][2][2];      // [iter parity][warp][{sumL, cntL}]

    const int n    = blockIdx.x;
    const int tid  = threadIdx.x;
    const int w    = tid >> 5;           // 0 or 1
    const int lane = tid & 31;

    const int chan = n / PTS;
    const int cx   = cxs[n];
    const int cy   = cys[n];
    const float* dch = disp + (size_t)chan * (HH * WW);
    const float* fch = fore + (size_t)chan * (HH * WW);
    const int    base = (cy << 10) + cx;          // WW == 1024

    // ---- validity (redundant in both warps; warp-uniform result):
    // maxpool3x3(|sobel_x(forepred)|)(cy,cx) > 3.1 && disp(cy,cx) > 0.007.
    // Centers >= 11 px from all borders. Lane l<25 loads the 5x5 window.
    const int r5 = lane / 5;
    const int c5 = lane - r5 * 5;
    float wv = 0.0f;
    if (lane < 25)
        wv = fch[(size_t)(cy + r5 - 2) * WW + (cx + c5 - 2)];
    float dC = 0.0f;
    if (lane == 25) dC = dch[base];
    dC = __shfl_sync(FULLM, dC, 25);

    const float wup = __shfl_sync(FULLM, wv, (lane + 27) & 31);   // lane-5
    const float wdn = __shfl_sync(FULLM, wv, (lane + 5)  & 31);   // lane+5
    const float cs  = wup + 2.0f * wv + wdn;
    const float csl = __shfl_sync(FULLM, cs, (lane + 31) & 31);   // lane-1
    const float csr = __shfl_sync(FULLM, cs, (lane + 1)  & 31);   // lane+1
    float gg = 0.0f;
    if (r5 >= 1 && r5 <= 3 && c5 >= 1 && c5 <= 3)
        gg = fabsf(csr - csl);
    const float g = __uint_as_float(__reduce_max_sync(FULLM, __float_as_uint(gg)));

    if (!((g > 3.1f) && (dC > 0.007f))) {
        if (tid == 0) { out[2 * n] = 0.0f; out[2 * n + 1] = 0.0f; }
        return;            // both warps exit before any __syncthreads
    }

    // ---- load the 15x23 disp window into padded smem (split by warp) -------
    // warp 0: rows 0..7, warp 1: rows 8..14
    #pragma unroll
    for (int i = 0; i < 8; i++) {
        const int r = (w << 3) + i;
        if (r < WROWS && lane < WCOLS)
            win[(r << 5) + lane] = dch[base + (r - 7) * WW + (lane - 11)];
    }
    __syncthreads();

    // ---- gather this warp's 1000 samples into registers via LDS ------------
    const int4* bx4p = (const int4*)(bxs + (size_t)n * DENSE) + w * CH_PER_W;
    const int4* by4p = (const int4*)(bys + (size_t)n * DENSE) + w * CH_PER_W;

    float sv[32];
    float mx = -1e30f, mn = 1e30f, stot = 0.0f;
    #pragma unroll
    for (int k = 0; k < 8; k++) {
        const int  j     = lane + (k << 5);
        const bool valid = (k < 7) || (j < CH_PER_W);   // compile-time true k<7
        float v0 = -1e30f, v1 = -1e30f, v2 = -1e30f, v3 = -1e30f;  // pads
        if (valid) {
            const int4 b4 = bx4p[j];
            const int4 y4 = by4p[j];
            // slot = (y+7)*32 + (x+11) = y*32 + x + 235
            v0 = win[(y4.x << 5) + b4.x + 235];
            v1 = win[(y4.y << 5) + b4.y + 235];
            v2 = win[(y4.z << 5) + b4.z + 235];
            v3 = win[(y4.w << 5) + b4.w + 235];
            mx = fmaxf(fmaxf(mx, v0), fmaxf(v1, fmaxf(v2, v3)));
            mn = fminf(fminf(mn, v0), fminf(v1, fminf(v2, v3)));
            stot += (v0 + v1) + (v2 + v3);
        }
        sv[4 * k + 0] = v0;
        sv[4 * k + 1] = v1;
        sv[4 * k + 2] = v2;
        sv[4 * k + 3] = v3;
    }
    // warp-level reduce, then cross-warp merge through smem
    #pragma unroll
    for (int o = 16; o; o >>= 1) {
        mx   = fmaxf(mx, __shfl_xor_sync(FULLM, mx, o));
        mn   = fminf(mn, __shfl_xor_sync(FULLM, mn, o));
        stot +=          __shfl_xor_sync(FULLM, stot, o);
    }
    if (lane == 0) { s_m[w][0] = mx; s_m[w][1] = mn; s_m[w][2] = stot; }
    __syncthreads();
    mx   = fmaxf(s_m[0][0], s_m[1][0]);
    mn   = fminf(s_m[0][1], s_m[1][1]);
    stot = s_m[0][2] + s_m[1][2];

    // ---- 2-cluster 1-D k-means on register samples, no atomics -------------
    // kL > kS => |s-kL|<=|s-kS| <=> s >= (kL+kS)/2 (midpoint tie -> large,
    // matching dl<=ds). disp > 0 => mid > 0 > -1e30 pads (never counted).
    // Both warps compute identical kL/kS from the merged sums -> identical
    // early-exit decision (bitwise fixed point == reference no-op iterations).
    float kL = mx, kS = mn;
    float lastCnt = 0.0f;
    #pragma unroll 1
    for (int it = 0; it < KMEAN; it++) {
        const float mid = 0.5f * (kL + kS);
        float s0 = 0.0f, s1 = 0.0f;
        int   ci = 0;
        #pragma unroll
        for (int k = 0; k < 32; k += 2) {
            const float a = sv[k], b = sv[k + 1];
            if (a >= mid) { s0 += a; ci++; }
            if (b >= mid) { s1 += b; ci++; }
        }
        float sumL = s0 + s1;
        #pragma unroll
        for (int o = 16; o; o >>= 1) sumL += __shfl_xor_sync(FULLM, sumL, o);
        const int cw = __reduce_add_sync(FULLM, ci);

        const int p = it & 1;                 // ping-pong buffer (no WAR race)
        if (lane == 0) { s_it[p][w][0] = sumL; s_it[p][w][1] = (float)cw; }
        __syncthreads();
        const float tsum = s_it[p][0][0] + s_it[p][1][0];
        const float tcnt = s_it[p][0][1] + s_it[p][1][1];

        const float nkL = __fdividef(tsum, tcnt);
        const float nkS = __fdividef(stot - tsum, (float)DENSE - tcnt);
        lastCnt = tcnt;
        const bool conv = (nkL == kL) && (nkS == kS);
        kL = nkL; kS = nkS;
        if (conv) break;                      // identical in both warps
    }

    const bool keep = ((kL - kS) > 0.005f) && (lastCnt > 5.0f);
    if (tid == 0) {
        const float kf = keep ? 1.0f : 0.0f;
        out[2 * n]     = kL * kf;
        out[2 * n + 1] = kS * kf;
    }
}

extern "C" void kernel_launch(void* const* d_in, const int* in_sizes, int n_in,
                              void* d_out, int out_size)
{
    const float* disp = (const float*)d_in[0];
    const float* fore = (const float*)d_in[1];
    const int*   cxs  = (const int*)  d_in[2];
    const int*   cys  = (const int*)  d_in[3];
    const int*   bxs  = (const int*)  d_in[4];
    const int*   bys  = (const int*)  d_in[5];
    float*       out  = (float*)d_out;

    rsbsp_kernel<<<NPTS, 64>>>(disp, fore, cxs, cys, bxs, bys, out);
}